// round 10
// baseline (speedup 1.0000x reference)
#include <cuda_runtime.h>
#include <cuda_bf16.h>
#include <cstdint>

#define NM     512
#define BATCH  32
#define DIMK   64
#define BIGF   1e30f
#define SENTU  0x7fc00000u

// Packed D (pre-scaled by log2 e): g_Dq[b][W][u][k] as float2.
// W = global warp row-group (rows 64W+2k, 64W+2k+1), u = local step, col j = u-2k.
#define UROWS 592
__device__ __align__(16) float g_Dq[(size_t)BATCH * 8 * UROWS * 64];

// Boundary rings: slot u holds producer-step-u value (row boundary col u-62).
// value(col j) lives at slot j+62. 656 slots: 576 written, rest preinit BIG.
#define RING 656
// Cross-CTA ring (row 255 -> 256) through global memory, one per batch.
__device__ float g_bnd[BATCH * RING];

__device__ __forceinline__ float ex2f(float x) {
    float r; asm("ex2.approx.f32 %0, %1;" : "=f"(r) : "f"(x)); return r;
}
__device__ __forceinline__ float lg2f(float x) {
    float r; asm("lg2.approx.f32 %0, %1;" : "=f"(r) : "f"(x)); return r;
}
// smem spin (raw backward branch, no BSSY): wait until *p != sentinel.
__device__ __forceinline__ float spinv(const float* p) {
    unsigned a = (unsigned)__cvta_generic_to_shared(p);
    unsigned v;
    asm volatile(
        "{\n\t.reg .pred sp;\n"
        "SPINS%=:\n\t"
        "ld.volatile.shared.b32 %0, [%1];\n\t"
        "setp.eq.u32 sp, %0, 0x7fc00000;\n\t"
        "@sp bra SPINS%=;\n\t}"
        : "=r"(v) : "r"(a) : "memory");
    return __uint_as_float(v);
}
__device__ __forceinline__ float gspinv(const float* p) {
    unsigned v;
    asm volatile(
        "{\n\t.reg .pred sp;\n"
        "SPING%=:\n\t"
        "ld.volatile.global.b32 %0, [%1];\n\t"
        "setp.eq.u32 sp, %0, 0x7fc00000;\n\t"
        "@sp bra SPING%=;\n\t}"
        : "=r"(v) : "l"(p) : "memory");
    return __uint_as_float(v);
}
__device__ __forceinline__ void sts_vol(float* p, float v) {
    unsigned a = (unsigned)__cvta_generic_to_shared(p);
    asm volatile("st.volatile.shared.b32 [%0], %1;" :: "r"(a), "f"(v) : "memory");
}
__device__ __forceinline__ void stg_vol(float* p, float v) {
    asm volatile("st.volatile.global.b32 [%0], %1;" :: "l"(p), "f"(v) : "memory");
}
__device__ __forceinline__ float vldg(const float* p) {
    float v;
    asm volatile("ld.volatile.global.b32 %0, [%1];" : "=f"(v) : "l"(p) : "memory");
    return v;
}

// ---------------------------------------------------------------------------
// Kernel 0: init cross-CTA global rings (sentinel for slots < 576, BIG above).
// ---------------------------------------------------------------------------
__global__ void binit_kernel()
{
    int t = blockIdx.x * 256 + threadIdx.x;
    if (t < BATCH * RING) {
        int s = t % RING;
        g_bnd[t] = (s < 576) ? __uint_as_float(SENTU) : BIGF;
    }
}

// ---------------------------------------------------------------------------
// Kernel 1: pairwise sqdist * log2(e) packed into g_Dq.
// 64x64 tiles (i-tile == global warp group W), 256 threads, 4x4 microtiles.
// ---------------------------------------------------------------------------
__global__ void __launch_bounds__(256) pairdist_kernel(
    const float* __restrict__ X, const float* __restrict__ Y)
{
    __shared__ __align__(16) float Xs[64 * 68];
    __shared__ __align__(16) float Ys[64 * 68];
    __shared__ __align__(16) float x2s[64];
    __shared__ __align__(16) float y2s[64];
    __shared__ __align__(16) float stage[64 * 66];   // stage[jl*66 + il]

    const int b  = blockIdx.z;
    const int i0 = blockIdx.x * 64;                  // W = blockIdx.x
    const int j0 = blockIdx.y * 64;
    const int tid = threadIdx.x;

    const float* Xb = X + ((size_t)b * NM + i0) * DIMK;
    const float* Yb = Y + ((size_t)b * NM + j0) * DIMK;

    for (int t = tid; t < 64 * 64; t += 256) {
        int r = t >> 6, k = t & 63;
        Xs[k * 68 + r] = Xb[r * DIMK + k];
        Ys[k * 68 + r] = Yb[r * DIMK + k];
    }
    __syncthreads();

    if (tid < 128) {
        int r = tid & 63;
        const float* S = (tid < 64) ? Xs : Ys;
        float acc = 0.f;
        #pragma unroll 8
        for (int k = 0; k < 64; ++k) { float v = S[k * 68 + r]; acc += v * v; }
        if (tid < 64) x2s[r] = acc; else y2s[r] = acc;
    }
    __syncthreads();

    const int tx = tid & 15, ty = tid >> 4;
    float acc[4][4];
    #pragma unroll
    for (int a = 0; a < 4; ++a)
        #pragma unroll
        for (int c = 0; c < 4; ++c) acc[a][c] = 0.f;

    #pragma unroll 8
    for (int k = 0; k < 64; ++k) {
        float4 xv = *(const float4*)&Xs[k * 68 + 4 * tx];
        float4 yv = *(const float4*)&Ys[k * 68 + 4 * ty];
        float xr[4] = {xv.x, xv.y, xv.z, xv.w};
        float yr[4] = {yv.x, yv.y, yv.z, yv.w};
        #pragma unroll
        for (int jj = 0; jj < 4; ++jj)
            #pragma unroll
            for (int ii = 0; ii < 4; ++ii)
                acc[jj][ii] += yr[jj] * xr[ii];
    }

    const float L2E = 1.4426950408889634f;
    float4 x2v = *(const float4*)&x2s[4 * tx];
    float xr2[4] = {x2v.x, x2v.y, x2v.z, x2v.w};
    #pragma unroll
    for (int jj = 0; jj < 4; ++jj) {
        float y2 = y2s[4 * ty + jj];
        #pragma unroll
        for (int ii = 0; ii < 4; ++ii)
            stage[(4 * ty + jj) * 66 + 4 * tx + ii] =
                (xr2[ii] + y2 - 2.f * acc[jj][ii]) * L2E;
    }
    __syncthreads();

    // Packed writeout: local step row c = jl + 2k; lane = k.
    const int wk   = tid >> 5;
    const int lane = tid & 31;
    float2* gout = (float2*)g_Dq + ((size_t)(b * 8 + blockIdx.x) * UROWS + j0) * 32;
    for (int c = wk; c < 126; c += 8) {
        int jl = c - 2 * lane;
        if ((unsigned)jl < 64u) {
            float2 p = *(const float2*)&stage[jl * 66 + 2 * lane];
            gout[(size_t)c * 32 + lane] = p;
        }
    }
}

// ---------------------------------------------------------------------------
// Kernel 2: soft-DTW, skew-2 wavefront, 2 CTAs per batch (4 warps each).
// CTA half h owns rows 256h..256h+255; lane k of warp w owns rows
// 256h+64w+2k, +1; local step u computes col j = u-2k.
// Intra-CTA seams: smem rings. Cross-CTA seam (row 255->256): global ring,
// consumer trails producer by ~61 steps so L2 latency is off-chain.
// ---------------------------------------------------------------------------
__global__ void __launch_bounds__(128, 1) sdtw_kernel(float* __restrict__ out)
{
    __shared__ __align__(16) float rings[4][RING];

    const int bx   = blockIdx.x;
    const int b    = bx >> 1;
    const int half = bx & 1;
    const int tid  = threadIdx.x;
    const int w    = tid >> 5;
    const int lane = tid & 31;
    const bool is31 = (lane == 31);

    for (int t = tid; t < 4 * RING; t += 128) {
        int r = t / RING, s = t % RING;
        bool sent = (r >= 1) && (s < 576);
        rings[0][t] = sent ? __uint_as_float(SENTU) : BIGF;   // flat fill
    }
    __syncthreads();

    // D prefetch ring (float2 per lane per step). Global warp id W = 4*half+w.
    const int W = 4 * half + w;
    const float2* dp0 = (const float2*)g_Dq + (size_t)(b * 8 + W) * UROWS * 32 + lane;
    float2 dring[8];
    #pragma unroll
    for (int p = 0; p < 8; ++p) dring[p] = dp0[p * 32];
    const float2* dp = dp0 + 8 * 32;

    const bool gpoll  = (half == 1) && (w == 0);   // consume from global ring
    const bool gstore = (half == 0) && (w == 3);   // produce into global ring
    const float* rring  = rings[w];
    float*       wring  = rings[(w + 1) & 3];      // w=3: unused (gstore path)
    const float* grring = g_bnd + b * RING;
    float*       gwring = g_bnd + b * RING;

    // Prefill boundary pipeline: value(col u) at slot u+62.
    float diagNow, upNow, upNext;
    if (gpoll) {
        diagNow = gspinv(grring + 61);
        upNow   = gspinv(grring + 62);
        upNext  = gspinv(grring + 63);
    } else {
        diagNow = spinv(rring + 61);
        upNow   = spinv(rring + 62);
        upNext  = spinv(rring + 63);
    }
    if (lane != 0) { diagNow = BIGF; upNow = BIGF; upNext = BIGF; }
    if (half == 0 && w == 0 && lane == 0) diagNow = 0.0f;   // origin R[-1][-1]=0

    float bnd[8];
    if (gpoll) {
        // robust chunk read: re-poll until no word is sentinel
        for (;;) {
            bool ok = true;
            #pragma unroll
            for (int q = 0; q < 8; ++q) {
                bnd[q] = vldg(grring + 64 + q);
                ok &= (__float_as_uint(bnd[q]) != SENTU);
            }
            if (ok) break;
        }
    } else {
        (void)spinv(rring + 71);
        float4 c0 = *(const float4*)(rring + 64);
        float4 c1 = *(const float4*)(rring + 68);
        bnd[0]=c0.x; bnd[1]=c0.y; bnd[2]=c0.z; bnd[3]=c0.w;
        bnd[4]=c1.x; bnd[5]=c1.y; bnd[6]=c1.z; bnd[7]=c1.w;
    }

    float lo0 = fminf(diagNow, upNow), hi0 = fmaxf(diagNow, upNow);
    float left0 = BIGF;
    float lo1 = BIGF, hi1 = BIGF;
    float res = 0.f;

    for (int B = 0; B < 576; B += 8) {
        #pragma unroll
        for (int x = 0; x < 8; ++x) {
            float2 d2 = dring[x];
            dring[x] = dp[x * 32];                     // prefetch step u+8

            // cell0: softmin(diag, up, left0); {lo0,hi0} precomputed
            float m0 = fminf(lo0, left0);
            float x0 = fmaxf(lo0, left0);
            float v0 = (d2.x + m0) - lg2f(ex2f(m0 - x0) + ex2f(m0 - hi0) + 1.0f);

            // cell1: softmin(left0_prev, v0, left1_prev); {lo1,hi1} precomputed
            float m1 = fminf(lo1, v0);
            float x1 = fmaxf(lo1, v0);
            float v1 = (d2.y + m1) - lg2f(ex2f(m1 - x1) + ex2f(m1 - hi1) + 1.0f);

            if (x == 5) { if (B == 568) res = v1; }    // u=573: row 511 col 511

            if (is31) {                                // publish row 64W+63
                if (gstore) stg_vol(gwring + (B + x), v1);
                else        sts_vol(wring + (B + x), v1);
            }

            float sh = __shfl_up_sync(0xffffffffu, v1, 1);
            float newv = (lane == 0) ? bnd[x] : sh;    // value(col u+2)

            if (x == 7) {                              // next boundary chunk
                if (gpoll) {
                    for (;;) {
                        bool ok = true;
                        #pragma unroll
                        for (int q = 0; q < 8; ++q) {
                            bnd[q] = vldg(grring + B + 72 + q);
                            ok &= (__float_as_uint(bnd[q]) != SENTU);
                        }
                        if (ok) break;
                    }
                } else {
                    (void)spinv(rring + B + 79);
                    float4 c0 = *(const float4*)(rring + B + 72);
                    float4 c1 = *(const float4*)(rring + B + 76);
                    bnd[0]=c0.x; bnd[1]=c0.y; bnd[2]=c0.z; bnd[3]=c0.w;
                    bnd[4]=c1.x; bnd[5]=c1.y; bnd[6]=c1.z; bnd[7]=c1.w;
                }
            }

            // roll pipeline (off the softmin chain)
            lo0 = fminf(upNow, upNext);
            hi0 = fmaxf(upNow, upNext);
            upNow = upNext; upNext = newv;
            lo1 = fminf(v0, v1); hi1 = fmaxf(v0, v1);
            left0 = v0;
        }
        dp += 8 * 32;
    }

    if (half == 1 && tid == 127)
        out[b] = res * 0.69314718055994531f;           // log2 -> natural domain
}

extern "C" void kernel_launch(void* const* d_in, const int* in_sizes, int n_in,
                              void* d_out, int out_size)
{
    (void)in_sizes; (void)n_in; (void)out_size;
    const float* X = (const float*)d_in[0];
    const float* Y = (const float*)d_in[1];
    float* out = (float*)d_out;

    binit_kernel<<<(BATCH * RING + 255) / 256, 256>>>();
    dim3 g1(NM / 64, NM / 64, BATCH);
    pairdist_kernel<<<g1, 256>>>(X, Y);
    sdtw_kernel<<<2 * BATCH, 128>>>(out);
}

// round 11
// speedup vs baseline: 1.5366x; 1.5366x over previous
#include <cuda_runtime.h>
#include <cuda_bf16.h>
#include <cstdint>

#define NM     512
#define BATCH  32
#define DIMK   64
#define BIGF   1e30f
#define SENTU  0x7fc00000u

// Packed D (pre-scaled by log2 e): g_Dq[b][W][u][k] as float2.
// W = warp row-group (rows 64W+2k, 64W+2k+1), u = local step, col j = u-2k.
#define UROWS 592
__device__ __align__(16) float g_Dq[(size_t)BATCH * 8 * UROWS * 64];

// Boundary rings: producer (warp w) publishes v1(u-1) at slot u.
// value(col c) lives at slot c+63. Slots 0..575 written; rest preinit BIG.
#define RING 656

__device__ __forceinline__ float ex2f(float x) {
    float r; asm("ex2.approx.f32 %0, %1;" : "=f"(r) : "f"(x)); return r;
}
__device__ __forceinline__ float lg2f(float x) {
    float r; asm("lg2.approx.f32 %0, %1;" : "=f"(r) : "f"(x)); return r;
}
// smem spin (raw backward branch, no BSSY): wait until *p != sentinel.
__device__ __forceinline__ float spinv(const float* p) {
    unsigned a = (unsigned)__cvta_generic_to_shared(p);
    unsigned v;
    asm volatile(
        "{\n\t.reg .pred sp;\n"
        "SPINS%=:\n\t"
        "ld.volatile.shared.b32 %0, [%1];\n\t"
        "setp.eq.u32 sp, %0, 0x7fc00000;\n\t"
        "@sp bra SPINS%=;\n\t}"
        : "=r"(v) : "r"(a) : "memory");
    return __uint_as_float(v);
}
__device__ __forceinline__ void sts_vol(float* p, float v) {
    unsigned a = (unsigned)__cvta_generic_to_shared(p);
    asm volatile("st.volatile.shared.b32 [%0], %1;" :: "r"(a), "f"(v) : "memory");
}

// ---------------------------------------------------------------------------
// Kernel 1: pairwise sqdist * log2(e) packed into g_Dq.
// 64x64 tiles (i-tile == warp row-group W), 256 threads, 4x4 microtiles.
// ---------------------------------------------------------------------------
__global__ void __launch_bounds__(256) pairdist_kernel(
    const float* __restrict__ X, const float* __restrict__ Y)
{
    __shared__ __align__(16) float Xs[64 * 68];
    __shared__ __align__(16) float Ys[64 * 68];
    __shared__ __align__(16) float x2s[64];
    __shared__ __align__(16) float y2s[64];
    __shared__ __align__(16) float stage[64 * 66];   // stage[jl*66 + il]

    const int b  = blockIdx.z;
    const int i0 = blockIdx.x * 64;                  // W = blockIdx.x
    const int j0 = blockIdx.y * 64;
    const int tid = threadIdx.x;

    const float* Xb = X + ((size_t)b * NM + i0) * DIMK;
    const float* Yb = Y + ((size_t)b * NM + j0) * DIMK;

    for (int t = tid; t < 64 * 64; t += 256) {
        int r = t >> 6, k = t & 63;
        Xs[k * 68 + r] = Xb[r * DIMK + k];
        Ys[k * 68 + r] = Yb[r * DIMK + k];
    }
    __syncthreads();

    if (tid < 128) {
        int r = tid & 63;
        const float* S = (tid < 64) ? Xs : Ys;
        float acc = 0.f;
        #pragma unroll 8
        for (int k = 0; k < 64; ++k) { float v = S[k * 68 + r]; acc += v * v; }
        if (tid < 64) x2s[r] = acc; else y2s[r] = acc;
    }
    __syncthreads();

    const int tx = tid & 15, ty = tid >> 4;
    float acc[4][4];
    #pragma unroll
    for (int a = 0; a < 4; ++a)
        #pragma unroll
        for (int c = 0; c < 4; ++c) acc[a][c] = 0.f;

    #pragma unroll 8
    for (int k = 0; k < 64; ++k) {
        float4 xv = *(const float4*)&Xs[k * 68 + 4 * tx];
        float4 yv = *(const float4*)&Ys[k * 68 + 4 * ty];
        float xr[4] = {xv.x, xv.y, xv.z, xv.w};
        float yr[4] = {yv.x, yv.y, yv.z, yv.w};
        #pragma unroll
        for (int jj = 0; jj < 4; ++jj)
            #pragma unroll
            for (int ii = 0; ii < 4; ++ii)
                acc[jj][ii] += yr[jj] * xr[ii];
    }

    const float L2E = 1.4426950408889634f;
    float4 x2v = *(const float4*)&x2s[4 * tx];
    float xr2[4] = {x2v.x, x2v.y, x2v.z, x2v.w};
    #pragma unroll
    for (int jj = 0; jj < 4; ++jj) {
        float y2 = y2s[4 * ty + jj];
        #pragma unroll
        for (int ii = 0; ii < 4; ++ii)
            stage[(4 * ty + jj) * 66 + 4 * tx + ii] =
                (xr2[ii] + y2 - 2.f * acc[jj][ii]) * L2E;
    }
    __syncthreads();

    // Packed writeout: local step row c = jl + 2k; lane = k.
    const int wk   = tid >> 5;
    const int lane = tid & 31;
    float2* gout = (float2*)g_Dq + ((size_t)(b * 8 + blockIdx.x) * UROWS + j0) * 32;
    for (int c = wk; c < 126; c += 8) {
        int jl = c - 2 * lane;
        if ((unsigned)jl < 64u) {
            float2 p = *(const float2*)&stage[jl * 66 + 2 * lane];
            gout[(size_t)c * 32 + lane] = p;
        }
    }
}

// ---------------------------------------------------------------------------
// Kernel 2: soft-DTW, skew-2 wavefront, software-pipelined. 1 CTA/batch,
// 8 warps. Lane k of warp w owns rows 64w+2k, +1; local step u covers col
// j = u-2k. Iteration u computes v0(u) AND v1(u-1): both depend only on
// v0(u-1), so their softmin chains overlap -> loop-carried chain = 52 cyc.
// ---------------------------------------------------------------------------
__global__ void __launch_bounds__(256, 1) sdtw_kernel(float* __restrict__ out)
{
    __shared__ __align__(16) float rings[9][RING];

    const int b    = blockIdx.x;
    const int tid  = threadIdx.x;
    const int w    = tid >> 5;
    const int lane = tid & 31;
    const bool is0  = (lane == 0);
    const bool is31 = (lane == 31);

    for (int t = tid; t < 9 * RING; t += 256) {
        int r = t / RING, s = t % RING;
        bool sent = (r >= 1) && (s < 576);
        rings[0][t] = sent ? __uint_as_float(SENTU) : BIGF;   // flat fill
    }
    __syncthreads();

    // D prefetch ring (float2 per lane per step).
    const float2* dp0 = (const float2*)g_Dq + (size_t)(b * 8 + w) * UROWS * 32 + lane;
    float2 dring[8];
    #pragma unroll
    for (int p = 0; p < 8; ++p) dring[p] = dp0[p * 32];
    const float2* dp = dp0 + 8 * 32;

    const float* rring = rings[w];       // consumer: value(col c) at slot c+63
    float*       wring = rings[w + 1];   // producer: iter u writes slot u

    // Prefill: P(-1) at slot 62, P(0) at slot 63.
    float pm1 = spinv(rring + 62);
    float p0  = spinv(rring + 63);
    if (lane != 0) { pm1 = BIGF; p0 = BIGF; }
    if (w == 0 && lane == 0) pm1 = 0.0f;      // origin: R[-1][-1] = 0
    float lo0  = fminf(pm1, p0), hi0 = fmaxf(pm1, p0);
    float pNow = p0;

    // First chunk: slots 64..71 = P(1..8) (newv(u)=P(u+1) for u=0..7).
    float bnd[8];
    {
        (void)spinv(rring + 71);
        float4 c0 = *(const float4*)(rring + 64);
        float4 c1 = *(const float4*)(rring + 68);
        bnd[0]=c0.x; bnd[1]=c0.y; bnd[2]=c0.z; bnd[3]=c0.w;
        bnd[4]=c1.x; bnd[5]=c1.y; bnd[6]=c1.z; bnd[7]=c1.w;
    }

    float v0p  = BIGF;                 // v0(u-1)
    float d2yp = 0.f;                  // d(u-1).y
    float lo1p = BIGF, hi1p = BIGF;    // min/max(v0(u-2), v1(u-2))
    float res  = 0.f;

    for (int B = 0; B < 576; B += 8) {
        #pragma unroll
        for (int x = 0; x < 8; ++x) {
            float2 d2 = dring[x];
            dring[x] = dp[x * 32];                 // prefetch step u+8

            // cell0(u): softmin(P(j-1), P(j), v0(u-1)) -- {lo0,hi0} precomputed
            float m0 = fminf(lo0, v0p);
            float x0 = fmaxf(lo0, v0p);
            float v0 = (d2.x + m0) - lg2f(ex2f(m0 - x0) + ex2f(m0 - hi0) + 1.0f);

            // cell1(u-1): softmin(v0(u-2), v1(u-2), v0(u-1)) -- independent of v0(u)
            float m1  = fminf(lo1p, v0p);
            float x1  = fmaxf(lo1p, v0p);
            float v1m = (d2yp + m1) - lg2f(ex2f(m1 - x1) + ex2f(m1 - hi1p) + 1.0f);

            if (x == 6) { if (B == 568) res = v1m; }   // iter 574 -> v1(573) = R[511][511]

            if (is31) sts_vol(wring + (B + x), v1m);   // publish slot u

            float sh = __shfl_up_sync(0xffffffffu, v1m, 1);
            float newv = is0 ? bnd[x] : sh;            // P(u+1)

            if (x == 7) {                              // next chunk: slots B+72..79
                (void)spinv(rring + B + 79);
                float4 c0 = *(const float4*)(rring + B + 72);
                float4 c1 = *(const float4*)(rring + B + 76);
                bnd[0]=c0.x; bnd[1]=c0.y; bnd[2]=c0.z; bnd[3]=c0.w;
                bnd[4]=c1.x; bnd[5]=c1.y; bnd[6]=c1.z; bnd[7]=c1.w;
            }

            // rolls (all off the v0 chain)
            lo1p = fminf(v0p, v1m);                    // min/max(v0(u-1), v1(u-1))
            hi1p = fmaxf(v0p, v1m);
            lo0  = fminf(pNow, newv);                  // min/max(P(j), P(j+1))
            hi0  = fmaxf(pNow, newv);
            pNow = newv;
            v0p  = v0;
            d2yp = d2.y;
        }
        dp += 8 * 32;
    }

    if (tid == 255)
        out[b] = res * 0.69314718055994531f;           // log2 -> natural domain
}

extern "C" void kernel_launch(void* const* d_in, const int* in_sizes, int n_in,
                              void* d_out, int out_size)
{
    (void)in_sizes; (void)n_in; (void)out_size;
    const float* X = (const float*)d_in[0];
    const float* Y = (const float*)d_in[1];
    float* out = (float*)d_out;

    dim3 g1(NM / 64, NM / 64, BATCH);
    pairdist_kernel<<<g1, 256>>>(X, Y);
    sdtw_kernel<<<BATCH, 256>>>(out);
}